// round 5
// baseline (speedup 1.0000x reference)
#include <cuda_runtime.h>
#include <mma.h>
#include <cstdint>

// Performer (FAVOR+) linear attention via wmma tf32 (m16n16k8) — sm_100 legacy tensor path.
// B=4 H=16 S=4096 D=64 M=64 fp32. Output fp32 (B,H,S,D).

using namespace nvcuda;

#define Sc 4096
#define BHc 64
#define L2E 1.4426950408889634f

__device__ float g_buf1[BHc * 64 * 65];

__global__ void zero_buf1() {
    int i = blockIdx.x * blockDim.x + threadIdx.x;
    if (i < BHc * 64 * 65) g_buf1[i] = 0.0f;
}

static __device__ __forceinline__ float ex2f(float x) {
    float r; asm("ex2.approx.ftz.f32 %0, %1;" : "=f"(r) : "f"(x)); return r;
}
#define TRUNC_HI(x) __uint_as_float(__float_as_uint(x) & 0xFFFFE000u)

template <typename Frag>
static __device__ __forceinline__ void cvt_tf32(Frag& f) {
    #pragma unroll
    for (int t = 0; t < f.num_elements; t++) f.x[t] = wmma::__float_to_tf32(f.x[t]);
}

typedef wmma::fragment<wmma::matrix_a, 16, 16, 8, wmma::precision::tf32, wmma::row_major> FragA;
typedef wmma::fragment<wmma::matrix_a, 16, 16, 8, wmma::precision::tf32, wmma::col_major> FragAT;
typedef wmma::fragment<wmma::matrix_b, 16, 16, 8, wmma::precision::tf32, wmma::row_major> FragB;
typedef wmma::fragment<wmma::accumulator, 16, 16, 8, float> FragC;

// ---- smem layout (float offsets). ld(X/W/KP)=72, ld(C/B1S/OUTS)=80.
#define O_WHI 0
#define O_WLO 4608            /* 64*72 */
#define O_XHI 9216
#define O_XLO 18432           /* +128*72 */
#define O_KP  27648           /* u, then kp/qp in place: [128][72] */
#define O_CS  36864           /* phase1: C tile [128][80]; phase2: unused */
#define O_B1S 47104           /* phase1: buf1 out [64][80]; phase2: b1 in [64][80] */
#define O_OUT 36864           /* phase2: out staging [128][80] (aliases O_CS) */
#define O_CEXP 52224          /* [128] */
#define SMEM_FLOATS 52352     /* 209408 bytes */

// ===========================================================================
// Common prologue: load W (hi/lo), X (hi/lo) + cexp. Stage A 3-pass. kp/qp in O_KP.
// ===========================================================================
static __device__ __forceinline__ void stageA_features(
    float* sm, const float* __restrict__ X, const float* __restrict__ W,
    int tid, int wid, bool loadW)
{
    // W -> [k][m] ld 72, hi/lo
    if (loadW) {
        for (int i = tid; i < 4096; i += 256) {
            int k = i >> 6, m = i & 63;
            float w = W[i];
            float hi = TRUNC_HI(w);
            sm[O_WHI + k * 72 + m] = hi;
            sm[O_WLO + k * 72 + m] = w - hi;
        }
    }
    // X -> hi/lo [r][c] ld 72, cexp
    {
        const int r = tid >> 1, cb = (tid & 1) * 32;
        float ss = 0.f;
        #pragma unroll
        for (int j = 0; j < 8; j++) {
            float4 x = *(const float4*)(X + r * 64 + cb + 4 * j);
            float4 h, l;
            h.x = TRUNC_HI(x.x); l.x = x.x - h.x;
            h.y = TRUNC_HI(x.y); l.y = x.y - h.y;
            h.z = TRUNC_HI(x.z); l.z = x.z - h.z;
            h.w = TRUNC_HI(x.w); l.w = x.w - h.w;
            ss = fmaf(x.x, x.x, ss); ss = fmaf(x.y, x.y, ss);
            ss = fmaf(x.z, x.z, ss); ss = fmaf(x.w, x.w, ss);
            *(float4*)&sm[O_XHI + r * 72 + cb + 4 * j] = h;
            *(float4*)&sm[O_XLO + r * 72 + cb + 4 * j] = l;
        }
        ss += __shfl_xor_sync(0xffffffffu, ss, 1);
        if ((tid & 1) == 0) sm[O_CEXP + r] = fmaf(ss, -0.5f * L2E, -3.0f);
    }
    __syncthreads();

    // stage A: u = X·W (3-pass tf32 split), warp tile 32x32 (2x2 of 16x16)
    {
        const int wm = (wid & 3) * 32;
        const int wn = (wid >> 2) * 32;
        FragC acc[2][2];
        #pragma unroll
        for (int i = 0; i < 2; i++)
            #pragma unroll
            for (int j = 0; j < 2; j++) wmma::fill_fragment(acc[i][j], 0.0f);

        #pragma unroll
        for (int k = 0; k < 8; k++) {
            FragA ah[2], al[2];
            FragB bh[2], bl[2];
            #pragma unroll
            for (int i = 0; i < 2; i++) {
                wmma::load_matrix_sync(ah[i], &sm[O_XHI + (wm + 16 * i) * 72 + k * 8], 72);
                wmma::load_matrix_sync(al[i], &sm[O_XLO + (wm + 16 * i) * 72 + k * 8], 72);
                cvt_tf32(ah[i]); cvt_tf32(al[i]);
            }
            #pragma unroll
            for (int j = 0; j < 2; j++) {
                wmma::load_matrix_sync(bh[j], &sm[O_WHI + k * 8 * 72 + wn + 16 * j], 72);
                wmma::load_matrix_sync(bl[j], &sm[O_WLO + k * 8 * 72 + wn + 16 * j], 72);
                cvt_tf32(bh[j]); cvt_tf32(bl[j]);
            }
            #pragma unroll
            for (int i = 0; i < 2; i++)
                #pragma unroll
                for (int j = 0; j < 2; j++) {
                    wmma::mma_sync(acc[i][j], ah[i], bh[j], acc[i][j]);
                    wmma::mma_sync(acc[i][j], ah[i], bl[j], acc[i][j]);
                    wmma::mma_sync(acc[i][j], al[i], bh[j], acc[i][j]);
                }
        }
        #pragma unroll
        for (int i = 0; i < 2; i++)
            #pragma unroll
            for (int j = 0; j < 2; j++)
                wmma::store_matrix_sync(&sm[O_KP + (wm + 16 * i) * 72 + wn + 16 * j],
                                        acc[i][j], 72, wmma::mem_row_major);
    }
    __syncthreads();

    // elementwise: kp = 2^(u*log2e + cexp)  (in place)
    for (int i = tid; i < 128 * 64; i += 256) {
        int r = i >> 6, m = i & 63;
        float u = sm[O_KP + r * 72 + m];
        sm[O_KP + r * 72 + m] = ex2f(fmaf(u, L2E, sm[O_CEXP + r]));
    }
    __syncthreads();
}

// ===========================================================================
__global__ __launch_bounds__(256, 1)
void phase1(const float* __restrict__ K, const float* __restrict__ V,
            const float* __restrict__ W) {
    extern __shared__ float sm[];
    const int tid = threadIdx.x, wid = tid >> 5;
    const int bh = blockIdx.y;
    const size_t base = ((size_t)bh * Sc + (size_t)blockIdx.x * 128) * 64;

    // C tile: [r][e] ld 80; e=64 -> 1, e=65..79 -> 0
    {
        const int r = tid >> 1, cb = (tid & 1) * 32;
        #pragma unroll
        for (int j = 0; j < 8; j++)
            *(float4*)&sm[O_CS + r * 80 + cb + 4 * j] = *(const float4*)(V + base + r * 64 + cb + 4 * j);
        if ((tid & 1) == 0) {
            sm[O_CS + r * 80 + 64] = 1.0f;
            #pragma unroll
            for (int j = 65; j < 80; j++) sm[O_CS + r * 80 + j] = 0.0f;
        }
    }

    stageA_features(sm, K + base, W, tid, wid, true);

    // stage C: buf1[m][e] = sum_r kp[r][m]*C[r][e]; A = kp^T (col_major from kp[r][m])
    for (int t = wid; t < 20; t += 8) {
        const int mt = t & 3, et = t >> 2;
        FragC acc;
        wmma::fill_fragment(acc, 0.0f);
        #pragma unroll
        for (int k = 0; k < 16; k++) {
            FragAT a;
            FragB b;
            wmma::load_matrix_sync(a, &sm[O_KP + k * 8 * 72 + mt * 16], 72);
            wmma::load_matrix_sync(b, &sm[O_CS + k * 8 * 80 + et * 16], 80);
            cvt_tf32(a); cvt_tf32(b);
            wmma::mma_sync(acc, a, b, acc);
        }
        wmma::store_matrix_sync(&sm[O_B1S + mt * 16 * 80 + et * 16], acc, 80, wmma::mem_row_major);
    }
    __syncthreads();

    for (int i = tid; i < 64 * 65; i += 256) {
        int m = i / 65, e = i - m * 65;
        atomicAdd(&g_buf1[((size_t)bh * 64 + m) * 65 + e], sm[O_B1S + m * 80 + e]);
    }
}

// ===========================================================================
__global__ __launch_bounds__(256, 1)
void phase2(const float* __restrict__ Q, const float* __restrict__ W,
            float* __restrict__ O) {
    extern __shared__ float sm[];
    const int tid = threadIdx.x, wid = tid >> 5;
    const int bh = blockIdx.y;
    const size_t base = ((size_t)bh * Sc + (size_t)blockIdx.x * 128) * 64;

    // b1s [m][e] ld 80 (pad cols 65..79 with 0)
    for (int i = tid; i < 64 * 80; i += 256) {
        int m = i / 80, e = i - m * 80;
        sm[O_B1S + i] = (e < 65) ? g_buf1[((size_t)bh * 64 + m) * 65 + e] : 0.0f;
    }

    stageA_features(sm, Q + base, W, tid, wid, true);

    // stage C': out[r][e] = sum_m qp[r][m]*b1[m][e]; warp wid owns m-rows [wid*16,+16)
    {
        FragC acc[5];
        #pragma unroll
        for (int j = 0; j < 5; j++) wmma::fill_fragment(acc[j], 0.0f);
        #pragma unroll
        for (int k = 0; k < 8; k++) {
            FragA a;
            wmma::load_matrix_sync(a, &sm[O_KP + wid * 16 * 72 + k * 8], 72);
            cvt_tf32(a);
            #pragma unroll
            for (int j = 0; j < 5; j++) {
                FragB b;
                wmma::load_matrix_sync(b, &sm[O_B1S + k * 8 * 80 + j * 16], 80);
                cvt_tf32(b);
                wmma::mma_sync(acc[j], a, b, acc[j]);
            }
        }
        __syncthreads();   // O_OUT aliases nothing live now (CS unused in phase2)
        #pragma unroll
        for (int j = 0; j < 5; j++)
            wmma::store_matrix_sync(&sm[O_OUT + wid * 16 * 80 + j * 16], acc[j], 80, wmma::mem_row_major);
    }
    __syncthreads();

    // divide by den (col 64) and store coalesced
    #pragma unroll
    for (int i = 0; i < 8; i++) {
        int idx = tid + 256 * i;
        int row = idx >> 4, c4 = (idx & 15) << 2;
        float inv = 1.0f / sm[O_OUT + row * 80 + 64];
        float4 v = *(const float4*)&sm[O_OUT + row * 80 + c4];
        v.x *= inv; v.y *= inv; v.z *= inv; v.w *= inv;
        *(float4*)(O + base + row * 64 + c4) = v;
    }
}

// ===========================================================================
extern "C" void kernel_launch(void* const* d_in, const int* in_sizes, int n_in,
                              void* d_out, int out_size) {
    const float* Q = (const float*)d_in[0];
    const float* K = (const float*)d_in[1];
    const float* V = (const float*)d_in[2];
    const float* W = (const float*)d_in[3];
    float* O = (float*)d_out;

    const int smem = SMEM_FLOATS * sizeof(float);   // 209408 B
    cudaFuncSetAttribute(phase1, cudaFuncAttributeMaxDynamicSharedMemorySize, smem);
    cudaFuncSetAttribute(phase2, cudaFuncAttributeMaxDynamicSharedMemorySize, smem);

    zero_buf1<<<(BHc * 64 * 65 + 255) / 256, 256>>>();
    phase1<<<dim3(32, BHc), 256, smem>>>(K, V, W);
    phase2<<<dim3(32, BHc), 256, smem>>>(Q, W, O);
}

// round 7
// speedup vs baseline: 1.1158x; 1.1158x over previous
#include <cuda_runtime.h>
#include <cstdint>

// Performer (FAVOR+) linear attention — packed fp32x2 FMA (Blackwell f32x2 path).
// B=4 H=16 S=4096 D=64 M=64 fp32. Output fp32 (B,H,S,D).

#define Sc 4096
#define BHc 64
#define L2E 1.4426950408889634f

__device__ float g_buf1[BHc * 64 * 65];

__global__ void zero_buf1() {
    int i = blockIdx.x * blockDim.x + threadIdx.x;
    if (i < BHc * 64 * 65) g_buf1[i] = 0.0f;
}

static __device__ __forceinline__ float ex2f(float x) {
    float r; asm("ex2.approx.ftz.f32 %0, %1;" : "=f"(r) : "f"(x)); return r;
}
static __device__ __forceinline__ unsigned long long rep2(float v) {
    unsigned long long r;
    asm("mov.b64 %0, {%1, %1};" : "=l"(r) : "f"(v));
    return r;
}
static __device__ __forceinline__ void fma2(unsigned long long& d,
                                            unsigned long long a, unsigned long long b) {
    asm("fma.rn.f32x2 %0, %1, %2, %0;" : "+l"(d) : "l"(a), "l"(b));
}
static __device__ __forceinline__ float lo32(unsigned long long v) {
    return __uint_as_float((unsigned)v);
}
static __device__ __forceinline__ float hi32(unsigned long long v) {
    return __uint_as_float((unsigned)(v >> 32));
}
static __device__ __forceinline__ float red2(unsigned long long v) {
    return lo32(v) + hi32(v);
}

// ---- smem layouts (float offsets) ----
// phase1: wp[32][64]f2 | xs[128][68] (K, then V) | kps[128][68] | cexp[128]
#define O_WP   0
#define O_XS   4096
#define O_KPS  12800
#define O_CEXP1 21504
#define SMEM1_FLOATS 21632      /* 86528 B  -> 2 CTAs/SM */
// phase2: wp | xs[128][68] (Q) | qps[128][68] | b1p[32][66]f2 | cexp
#define O_QPS  12800
#define O_B1P  21504
#define O_CEXP2 25728
#define SMEM2_FLOATS 25856      /* 103424 B -> 2 CTAs/SM */

// ===========================================================================
// Shared: load W (k-pair-interleaved), X (+cexp); stage A (X·Ω, k-paired fp32x2);
// stage B (exp) -> feat tile [128][68].
// ===========================================================================
static __device__ __forceinline__ void stageAB(
    float* sm, const float* __restrict__ X, const float* __restrict__ W,
    int tid, int o_cexp)
{
    // W -> wp[k2][m] = (W[2k2][m], W[2k2+1][m]) ; float off k2*128 + 2m
    for (int i = tid; i < 2048; i += 256) {
        int k2 = i >> 6, m = i & 63;
        sm[O_WP + k2 * 128 + 2 * m]     = W[(2 * k2) * 64 + m];
        sm[O_WP + k2 * 128 + 2 * m + 1] = W[(2 * k2 + 1) * 64 + m];
    }
    // X -> xs[r][68], cexp[r] = -0.5*|x|^2*log2e - 3
    {
        const int r = tid >> 1, cb = (tid & 1) * 32;
        float ss = 0.f;
        #pragma unroll
        for (int j = 0; j < 8; j++) {
            float4 x = *(const float4*)(X + r * 64 + cb + 4 * j);
            ss = fmaf(x.x, x.x, ss); ss = fmaf(x.y, x.y, ss);
            ss = fmaf(x.z, x.z, ss); ss = fmaf(x.w, x.w, ss);
            *(float4*)&sm[O_XS + r * 68 + cb + 4 * j] = x;
        }
        ss += __shfl_xor_sync(0xffffffffu, ss, 1);
        if ((tid & 1) == 0) sm[o_cexp + r] = fmaf(ss, -0.5f * L2E, -3.0f);
    }
    __syncthreads();

    // stage A: u[r][m] = sum_k x[r][k] w[k][m]; tile r4 (strided 32) x m8
    const int tc = tid & 7, tr = tid >> 3;       // m0 = 8*tc, rows = tr + 32*i
    unsigned long long acc[4][8] = {};
    #pragma unroll 4
    for (int kq = 0; kq < 16; kq++) {
        ulonglong2 a[4];
        #pragma unroll
        for (int i = 0; i < 4; i++)
            a[i] = *(const ulonglong2*)&sm[O_XS + (tr + 32 * i) * 68 + 4 * kq];
        ulonglong2 b0[4], b1[4];
        #pragma unroll
        for (int j = 0; j < 4; j++) {
            b0[j] = *(const ulonglong2*)&sm[O_WP + (2 * kq) * 128 + 16 * tc + 4 * j];
            b1[j] = *(const ulonglong2*)&sm[O_WP + (2 * kq + 1) * 128 + 16 * tc + 4 * j];
        }
        #pragma unroll
        for (int i = 0; i < 4; i++)
            #pragma unroll
            for (int j = 0; j < 4; j++) {
                fma2(acc[i][2 * j],     a[i].x, b0[j].x);
                fma2(acc[i][2 * j + 1], a[i].x, b0[j].y);
                fma2(acc[i][2 * j],     a[i].y, b1[j].x);
                fma2(acc[i][2 * j + 1], a[i].y, b1[j].y);
            }
    }
    // stage B: kp = 2^(u*log2e + cexp) -> kps[r][68]
    #pragma unroll
    for (int i = 0; i < 4; i++) {
        int r = tr + 32 * i;
        float ce = sm[o_cexp + r];
        float4 v0, v1;
        v0.x = ex2f(fmaf(red2(acc[i][0]), L2E, ce));
        v0.y = ex2f(fmaf(red2(acc[i][1]), L2E, ce));
        v0.z = ex2f(fmaf(red2(acc[i][2]), L2E, ce));
        v0.w = ex2f(fmaf(red2(acc[i][3]), L2E, ce));
        v1.x = ex2f(fmaf(red2(acc[i][4]), L2E, ce));
        v1.y = ex2f(fmaf(red2(acc[i][5]), L2E, ce));
        v1.z = ex2f(fmaf(red2(acc[i][6]), L2E, ce));
        v1.w = ex2f(fmaf(red2(acc[i][7]), L2E, ce));
        *(float4*)&sm[O_KPS + r * 68 + 8 * tc]     = v0;
        *(float4*)&sm[O_KPS + r * 68 + 8 * tc + 4] = v1;
    }
    __syncthreads();
}

// ===========================================================================
__global__ __launch_bounds__(256, 2)
void phase1(const float* __restrict__ K, const float* __restrict__ V,
            const float* __restrict__ W) {
    extern __shared__ float sm[];
    const int tid = threadIdx.x;
    const int bh = blockIdx.y;
    const size_t base = ((size_t)bh * Sc + (size_t)blockIdx.x * 128) * 64;

    stageAB(sm, K + base, W, tid, O_CEXP1);

    // V -> xs (K tile is dead)
    {
        const int r = tid >> 1, cb = (tid & 1) * 32;
        #pragma unroll
        for (int j = 0; j < 8; j++)
            *(float4*)&sm[O_XS + r * 68 + cb + 4 * j] =
                *(const float4*)(V + base + r * 64 + cb + 4 * j);
    }
    __syncthreads();

    // stage C: buf1[m][e] += sum_r kp[r][m] * V[r][e]; m-paired, e replicated
    {
        const int half = tid >> 7, t = tid & 127;
        const int tm = t >> 4, te = t & 15;       // m0 = 8*tm, e0 = 4*te
        unsigned long long acc[4][4] = {};
        const int rbeg = half * 64;
        #pragma unroll 4
        for (int rr = 0; rr < 64; rr++) {
            int r = rbeg + rr;
            unsigned long long a[4];
            #pragma unroll
            for (int p = 0; p < 4; p++)
                a[p] = *(const unsigned long long*)&sm[O_KPS + r * 68 + 8 * tm + 2 * p];
            float4 c4 = *(const float4*)&sm[O_XS + r * 68 + 4 * te];
            unsigned long long b0 = rep2(c4.x), b1 = rep2(c4.y);
            unsigned long long b2 = rep2(c4.z), b3 = rep2(c4.w);
            #pragma unroll
            for (int p = 0; p < 4; p++) {
                fma2(acc[p][0], a[p], b0);
                fma2(acc[p][1], a[p], b1);
                fma2(acc[p][2], a[p], b2);
                fma2(acc[p][3], a[p], b3);
            }
        }
        float* dst = g_buf1 + ((size_t)bh * 64 + 8 * tm) * 65 + 4 * te;
        #pragma unroll
        for (int p = 0; p < 4; p++)
            #pragma unroll
            for (int j = 0; j < 4; j++) {
                atomicAdd(&dst[(2 * p) * 65 + j],     lo32(acc[p][j]));
                atomicAdd(&dst[(2 * p + 1) * 65 + j], hi32(acc[p][j]));
            }
    }
    // denominator column: buf1[m][64] += sum_r kp[r][m]
    if (tid < 128) {
        int m = tid & 63, h = tid >> 6;
        float s = 0.f;
        #pragma unroll 8
        for (int rr = 0; rr < 64; rr++) s += sm[O_KPS + (h * 64 + rr) * 68 + m];
        atomicAdd(&g_buf1[((size_t)bh * 64 + m) * 65 + 64], s);
    }
}

// ===========================================================================
__global__ __launch_bounds__(256, 2)
void phase2(const float* __restrict__ Q, const float* __restrict__ W,
            float* __restrict__ O) {
    extern __shared__ float sm[];
    const int tid = threadIdx.x;
    const int bh = blockIdx.y;
    const size_t base = ((size_t)bh * Sc + (size_t)blockIdx.x * 128) * 64;

    // buf1 -> b1p[m2][d] = (buf1[2m2][d], buf1[2m2+1][d]); float off m2*132 + 2d
    for (int i = tid; i < 32 * 65; i += 256) {
        int m2 = i / 65, d = i - m2 * 65;
        const float* src = g_buf1 + ((size_t)bh * 64 + 2 * m2) * 65 + d;
        sm[O_B1P + m2 * 132 + 2 * d]     = src[0];
        sm[O_B1P + m2 * 132 + 2 * d + 1] = src[65];
    }

    stageAB(sm, Q + base, W, tid, O_CEXP2);   // qp -> sm[O_QPS==O_KPS]

    // stage C': out[r][d] = sum_m qp[r][m] b1[m][d] / den; m-paired both sides
    {
        const int tc = tid & 7, tr = tid >> 3;    // d0 = 8*tc, rows = tr + 32*i
        unsigned long long acc[4][8] = {}, accd[4] = {};
        #pragma unroll 4
        for (int kq = 0; kq < 16; kq++) {
            ulonglong2 a[4];
            #pragma unroll
            for (int i = 0; i < 4; i++)
                a[i] = *(const ulonglong2*)&sm[O_QPS + (tr + 32 * i) * 68 + 4 * kq];
            ulonglong2 b0[4], b1[4];
            #pragma unroll
            for (int j = 0; j < 4; j++) {
                b0[j] = *(const ulonglong2*)&sm[O_B1P + (2 * kq) * 132 + 16 * tc + 4 * j];
                b1[j] = *(const ulonglong2*)&sm[O_B1P + (2 * kq + 1) * 132 + 16 * tc + 4 * j];
            }
            unsigned long long bd0 = *(const unsigned long long*)&sm[O_B1P + (2 * kq) * 132 + 128];
            unsigned long long bd1 = *(const unsigned long long*)&sm[O_B1P + (2 * kq + 1) * 132 + 128];
            #pragma unroll
            for (int i = 0; i < 4; i++) {
                #pragma unroll
                for (int j = 0; j < 4; j++) {
                    fma2(acc[i][2 * j],     a[i].x, b0[j].x);
                    fma2(acc[i][2 * j + 1], a[i].x, b0[j].y);
                    fma2(acc[i][2 * j],     a[i].y, b1[j].x);
                    fma2(acc[i][2 * j + 1], a[i].y, b1[j].y);
                }
                fma2(accd[i], a[i].x, bd0);
                fma2(accd[i], a[i].y, bd1);
            }
        }
        #pragma unroll
        for (int i = 0; i < 4; i++) {
            int r = tr + 32 * i;
            float inv = 1.0f / red2(accd[i]);
            float4 o0, o1;
            o0.x = red2(acc[i][0]) * inv; o0.y = red2(acc[i][1]) * inv;
            o0.z = red2(acc[i][2]) * inv; o0.w = red2(acc[i][3]) * inv;
            o1.x = red2(acc[i][4]) * inv; o1.y = red2(acc[i][5]) * inv;
            o1.z = red2(acc[i][6]) * inv; o1.w = red2(acc[i][7]) * inv;
            *(float4*)(O + base + r * 64 + 8 * tc)     = o0;
            *(float4*)(O + base + r * 64 + 8 * tc + 4) = o1;
        }
    }
}

// ===========================================================================
extern "C" void kernel_launch(void* const* d_in, const int* in_sizes, int n_in,
                              void* d_out, int out_size) {
    const float* Q = (const float*)d_in[0];
    const float* K = (const float*)d_in[1];
    const float* V = (const float*)d_in[2];
    const float* W = (const float*)d_in[3];
    float* O = (float*)d_out;

    const int smem1 = SMEM1_FLOATS * sizeof(float);   // 86528 B
    const int smem2 = SMEM2_FLOATS * sizeof(float);   // 103424 B
    cudaFuncSetAttribute(phase1, cudaFuncAttributeMaxDynamicSharedMemorySize, smem1);
    cudaFuncSetAttribute(phase2, cudaFuncAttributeMaxDynamicSharedMemorySize, smem2);

    zero_buf1<<<(BHc * 64 * 65 + 255) / 256, 256>>>();
    phase1<<<dim3(32, BHc), 256, smem1>>>(K, V, W);
    phase2<<<dim3(32, BHc), 256, smem2>>>(Q, W, O);
}